// round 9
// baseline (speedup 1.0000x reference)
#include <cuda_runtime.h>
#include <cuda_bf16.h>
#include <stdint.h>

#define NN 100000
#define NE 1600000
#define HID 128

#define SCHUNK 512
#define NCHUNK ((NN + SCHUNK - 1) / SCHUNK)

// ---------------- device scratch ----------------
__device__ int   g_src[NE];
__device__ int   g_dst[NE];
__device__ float g_dis[NN];            // deg (init 1.0 self-loop), then rsqrt(deg)
__device__ int   g_cursor[NN];         // in-degree count, then CSR fill cursor
__device__ int   g_rowptr[NN + 1];
__device__ int   g_csrsrc[NE];
__device__ float g_csrcoef[NE];
__device__ float g_a1[NN];             // layer-1 scalar aggregation
__device__ __align__(16) float g_h1[(size_t)NN * HID];
__device__ __align__(16) float g_agg[(size_t)NN * HID];
__device__ int   g_ticket;
__device__ int   g_state[NCHUNK];      // scan lookback: 0 = pending, else total+1

// ---------------- packed fp32x2 helpers ----------------
__device__ __forceinline__ unsigned long long pk2(float lo, float hi) {
    unsigned long long r;
    asm("mov.b64 %0, {%1,%2};" : "=l"(r) : "f"(lo), "f"(hi));
    return r;
}
__device__ __forceinline__ unsigned long long ffma2(unsigned long long a,
                                                    unsigned long long b,
                                                    unsigned long long c) {
    unsigned long long d;
    asm("fma.rn.f32x2 %0, %1, %2, %3;" : "=l"(d) : "l"(a), "l"(b), "l"(c));
    return d;
}
__device__ __forceinline__ void upk2(unsigned long long v, float& lo, float& hi) {
    asm("mov.b64 {%0,%1}, %2;" : "=f"(lo), "=f"(hi) : "l"(v));
}

// ---------------- K1: init ----------------
__global__ void k_init(void) {
    int i = blockIdx.x * blockDim.x + threadIdx.x;
    if (i < NN) { g_dis[i] = 1.0f; g_cursor[i] = 0; g_a1[i] = 0.f; }
    if (i < NCHUNK) g_state[i] = 0;
    if (i == 0) g_ticket = 0;
}

// ---------------- K2: convert (inline dtype detect) + degree ----------------
__global__ void k_conv_deg(const void* ei, const float* __restrict__ w) {
    __shared__ int sflag;
    int t = threadIdx.x;
    if (t < 32) {
        const long long* p = (const long long*)ei;
        long long v = p[(long long)t * (NE / 32)];
        bool ok = (v >= 0 && v < NN);
        unsigned m = __ballot_sync(0xFFFFFFFFu, ok);
        if (t == 0) sflag = (m == 0xFFFFFFFFu) ? 1 : 0;
    }
    __syncthreads();
    int e = blockIdx.x * blockDim.x + t;
    if (e >= NE) return;
    int s, d;
    if (sflag) {
        const long long* p = (const long long*)ei;
        s = (int)p[e]; d = (int)p[e + NE];
    } else {
        const int* p = (const int*)ei;
        s = p[e]; d = p[e + NE];
    }
    g_src[e] = s; g_dst[e] = d;
    atomicAdd(&g_dis[d], w[e]);
    atomicAdd(&g_cursor[d], 1);
}

// ---------------- K3: single-pass scan (decoupled lookback) + rsqrt ----------
__global__ void k_scan(void) {       // <<<NCHUNK, SCHUNK>>>
    __shared__ int sh[SCHUNK];
    __shared__ int sbid, soff;
    int t = threadIdx.x;
    if (t == 0) sbid = atomicAdd(&g_ticket, 1);
    __syncthreads();
    int bid = sbid;
    int idx = bid * SCHUNK + t;
    int v = (idx < NN) ? g_cursor[idx] : 0;
    sh[t] = v;
    __syncthreads();
    for (int off = 1; off < SCHUNK; off <<= 1) {
        int u = (t >= off) ? sh[t - off] : 0;
        __syncthreads();
        sh[t] += u;
        __syncthreads();
    }
    if (t == 0) atomicExch(&g_state[bid], sh[SCHUNK - 1] + 1);  // publish total
    if (t < 32) {                                                // lookback
        int acc = 0;
        for (int b = t; b < bid; b += 32) {
            int s;
            while ((s = atomicAdd(&g_state[b], 0)) == 0) {}
            acc += s - 1;
        }
        #pragma unroll
        for (int o = 16; o; o >>= 1) acc += __shfl_xor_sync(0xFFFFFFFFu, acc, o);
        if (t == 0) soff = acc;
    }
    __syncthreads();
    if (idx < NN) {
        int r = sh[t] - v + soff;     // exclusive global scan
        g_rowptr[idx] = r;
        g_cursor[idx] = r;
        g_dis[idx] = rsqrtf(g_dis[idx]);
    }
    if (bid == 0 && t == 0) g_rowptr[NN] = NE;
}

// ---------------- K4: CSR fill + layer-1 scalar aggregation -------------------
__global__ void k_fill(const float* __restrict__ w, const float* __restrict__ x) {
    int e = blockIdx.x * blockDim.x + threadIdx.x;
    if (e >= NE) return;
    int d = g_dst[e], s = g_src[e];
    float c = g_dis[s] * w[e] * g_dis[d];
    int pos = atomicAdd(&g_cursor[d], 1);
    g_csrsrc[pos]  = s;
    g_csrcoef[pos] = c;
    atomicAdd(&g_a1[d], c * __ldg(&x[s]));
}

// ---------------- K5: expand scalar a1 -> h1 (warp per node) ------------------
__global__ void k_expand(const float* __restrict__ x,
                         const float* __restrict__ W1,
                         const float* __restrict__ b1) {
    int gt = blockIdx.x * blockDim.x + threadIdx.x;
    int node = gt >> 5, lane = gt & 31;
    if (node >= NN) return;
    float dd = g_dis[node];
    float a  = g_a1[node] + dd * dd * x[node];
    size_t base = (size_t)node * HID;
    #pragma unroll
    for (int k = 0; k < 4; k++) {
        int f = lane + 32 * k;
        g_h1[base + f] = fmaxf(fmaf(a, W1[f], b1[f]), 0.f);
    }
}

// ---------------- K6: layer-2 SpMM, block per node, smem-staged edges ---------
// thread f accumulates feature f; edges staged coalesced into smem, inner loop
// unrolled x4 so 4 independent coalesced 512B h1-row loads are in flight.
__global__ __launch_bounds__(HID) void k_agg(void) {   // <<<NN, 128>>>
    __shared__ int   s_src[HID];
    __shared__ float s_cf[HID];
    int node = blockIdx.x;
    int f = threadIdx.x;
    float dd = g_dis[node];
    float acc = dd * dd * g_h1[(size_t)node * HID + f];
    int s0 = g_rowptr[node], s1 = g_rowptr[node + 1];
    for (int base = s0; base < s1; base += HID) {
        int m = min(HID, s1 - base);
        __syncthreads();
        if (f < m) { s_src[f] = g_csrsrc[base + f]; s_cf[f] = g_csrcoef[base + f]; }
        __syncthreads();
        int k = 0;
        for (; k + 4 <= m; k += 4) {
            int   i0 = s_src[k],   i1 = s_src[k+1],   i2 = s_src[k+2],   i3 = s_src[k+3];
            float c0 = s_cf[k],    c1 = s_cf[k+1],    c2 = s_cf[k+2],    c3 = s_cf[k+3];
            float h0 = g_h1[(size_t)i0 * HID + f];
            float h1v = g_h1[(size_t)i1 * HID + f];
            float h2v = g_h1[(size_t)i2 * HID + f];
            float h3v = g_h1[(size_t)i3 * HID + f];
            acc = fmaf(c0, h0, acc);
            acc = fmaf(c1, h1v, acc);
            acc = fmaf(c2, h2v, acc);
            acc = fmaf(c3, h3v, acc);
        }
        for (; k < m; k++)
            acc = fmaf(s_cf[k], g_h1[(size_t)s_src[k] * HID + f], acc);
    }
    g_agg[(size_t)node * HID + f] = acc;
}

// ---------------- K7: fused MLP head, packed f32x2 ----------------------------
#define NT  16
#define NTP 18   // +2 pad: kills bank conflicts, keeps 8B alignment
__global__ __launch_bounds__(256) void k_mlp(
        const float* __restrict__ W2,  const float* __restrict__ b2,
        const float* __restrict__ Wl1, const float* __restrict__ bl1,
        const float* __restrict__ Wl2, const float* __restrict__ bl2,
        float* __restrict__ out) {     // <<<ceil(NN/NT), 256>>>
    __shared__ __align__(16) float vshT[HID][NTP];       // transposed agg tile
    __shared__ __align__(16) float h2T[2 * HID][NTP];    // transposed h2
    __shared__ __align__(16) float h3sh[NT][HID];
    int base = blockIdx.x * NT;
    int t = threadIdx.x;

    for (int i = t; i < NT * HID; i += 256) {
        int n = i >> 7, f = i & 127;
        int node = base + n;
        vshT[f][n] = (node < NN) ? g_agg[(size_t)node * HID + f] : 0.f;
    }
    __syncthreads();

    // phase 1: h2[c=t] = relu(sum_f agg[n][f] * W2[f][c] + b2[c]), node-pairs packed
    {
        float bb = b2[t];
        unsigned long long acc[NT / 2];
        unsigned long long bp = pk2(bb, bb);
        #pragma unroll
        for (int i = 0; i < NT / 2; i++) acc[i] = bp;
        #pragma unroll 2
        for (int f = 0; f < HID; f++) {
            float wf = W2[f * 256 + t];
            unsigned long long wp = pk2(wf, wf);
            const unsigned long long* row = (const unsigned long long*)&vshT[f][0];
            #pragma unroll
            for (int i = 0; i < NT / 2; i++) acc[i] = ffma2(row[i], wp, acc[i]);
        }
        #pragma unroll
        for (int i = 0; i < NT / 2; i++) {
            float lo, hi; upk2(acc[i], lo, hi);
            h2T[t][2 * i]     = fmaxf(lo, 0.f);
            h2T[t][2 * i + 1] = fmaxf(hi, 0.f);
        }
    }
    __syncthreads();

    // phase 2: h3[g] = relu(sum_c h2[n][c] * Wl1[c][g] + bl1[g]); 2 halves x 8 nodes
    {
        int g = t & 127, nb = (t >> 7) * 8;
        float bb = bl1[g];
        unsigned long long acc[4];
        unsigned long long bp = pk2(bb, bb);
        #pragma unroll
        for (int i = 0; i < 4; i++) acc[i] = bp;
        #pragma unroll 2
        for (int c = 0; c < 2 * HID; c++) {
            float wl = Wl1[c * HID + g];
            unsigned long long wp = pk2(wl, wl);
            const unsigned long long* row = (const unsigned long long*)&h2T[c][nb];
            #pragma unroll
            for (int i = 0; i < 4; i++) acc[i] = ffma2(row[i], wp, acc[i]);
        }
        #pragma unroll
        for (int i = 0; i < 4; i++) {
            float lo, hi; upk2(acc[i], lo, hi);
            h3sh[nb + 2 * i][g]     = fmaxf(lo, 0.f);
            h3sh[nb + 2 * i + 1][g] = fmaxf(hi, 0.f);
        }
    }
    __syncthreads();

    // phase 3: out[n] = h3[n] . Wl2 + bl2 ; warp per 2 nodes
    {
        int warp = t >> 5, lane = t & 31;
        #pragma unroll
        for (int rep = 0; rep < 2; rep++) {
            int n = warp * 2 + rep;
            int node = base + n;
            float s = 0.f;
            #pragma unroll
            for (int q = 0; q < 4; q++)
                s = fmaf(h3sh[n][lane + 32 * q], Wl2[lane + 32 * q], s);
            #pragma unroll
            for (int o = 16; o; o >>= 1) s += __shfl_xor_sync(0xFFFFFFFFu, s, o);
            if (lane == 0 && node < NN) out[node] = s + bl2[0];
        }
    }
}

// ---------------- launch ---------------------------------------------------------
extern "C" void kernel_launch(void* const* d_in, const int* in_sizes, int n_in,
                              void* d_out, int out_size) {
    const float* x   = (const float*)d_in[0];
    const void*  ei  = d_in[1];
    const float* w   = (const float*)d_in[2];
    const float* W1  = (const float*)d_in[3];
    const float* b1  = (const float*)d_in[4];
    const float* W2  = (const float*)d_in[5];
    const float* b2  = (const float*)d_in[6];
    const float* Wl1 = (const float*)d_in[7];
    const float* bl1 = (const float*)d_in[8];
    const float* Wl2 = (const float*)d_in[9];
    const float* bl2 = (const float*)d_in[10];
    float* out = (float*)d_out;

    const int TB = 256;
    const int EB = (NE + TB - 1) / TB;
    const int VB = (NN + TB - 1) / TB;

    k_init    <<<VB, TB>>>();
    k_conv_deg<<<EB, TB>>>(ei, w);
    k_scan    <<<NCHUNK, SCHUNK>>>();
    k_fill    <<<EB, TB>>>(w, x);
    k_expand  <<<(NN * 32 + TB - 1) / TB, TB>>>(x, W1, b1);
    k_agg     <<<NN, HID>>>();
    k_mlp     <<<(NN + NT - 1) / NT, TB>>>(W2, b2, Wl1, bl1, Wl2, bl2, out);
}

// round 12
// speedup vs baseline: 2.3487x; 2.3487x over previous
#include <cuda_runtime.h>
#include <cuda_bf16.h>
#include <stdint.h>

#define NN 100000
#define NE 1600000
#define HID 128

// ---------------- device scratch ----------------
__device__ int   g_src[NE];
__device__ int   g_dst[NE];
__device__ float g_dis[NN];
__device__ int   g_cursor[NN];
__device__ int   g_rowptr[NN + 1];
__device__ int   g_partials[256];
__device__ int   g_csrsrc[NE];
__device__ float g_csrcoef[NE];
__device__ __align__(16) float g_h1[(size_t)NN * HID];
__device__ __align__(16) float g_agg[(size_t)NN * HID];
__device__ int g_flag64;
// pre-split transposed weights (bf16 hi/lo)
__device__ __align__(16) unsigned short g_W2T_hi[256 * 128];
__device__ __align__(16) unsigned short g_W2T_lo[256 * 128];
__device__ __align__(16) unsigned short g_Wl1T_hi[128 * 256];
__device__ __align__(16) unsigned short g_Wl1T_lo[128 * 256];

// ================= R1 front-end (known-good 780us baseline) ==================
__global__ void k_detect(const void* ei) {
    const long long* p = (const long long*)ei;
    int lane = threadIdx.x;
    long long v = p[(long long)lane * (NE / 32)];
    bool ok = (v >= 0 && v < NN);
    unsigned m = __ballot_sync(0xFFFFFFFFu, ok);
    if (lane == 0) g_flag64 = (m == 0xFFFFFFFFu) ? 1 : 0;
}
__global__ void k_convert(const void* ei) {
    int e = blockIdx.x * blockDim.x + threadIdx.x;
    if (e >= NE) return;
    if (g_flag64) {
        const long long* p = (const long long*)ei;
        g_src[e] = (int)p[e]; g_dst[e] = (int)p[e + NE];
    } else {
        const int* p = (const int*)ei;
        g_src[e] = p[e]; g_dst[e] = p[e + NE];
    }
}
__global__ void k_init(void) {
    int i = blockIdx.x * blockDim.x + threadIdx.x;
    if (i < NN) { g_dis[i] = 1.0f; g_cursor[i] = 0; }
}
__global__ void k_deg(const float* __restrict__ w) {
    int e = blockIdx.x * blockDim.x + threadIdx.x;
    if (e >= NE) return;
    int d = g_dst[e];
    atomicAdd(&g_dis[d], w[e]);
    atomicAdd(&g_cursor[d], 1);
}
__global__ void k_rsqrt(void) {
    int i = blockIdx.x * blockDim.x + threadIdx.x;
    if (i < NN) g_dis[i] = rsqrtf(g_dis[i]);
}
#define SCHUNK 512
#define NCHUNK ((NN + SCHUNK - 1) / SCHUNK)
__global__ void k_scan1(void) {
    __shared__ int sh[SCHUNK];
    int t = threadIdx.x;
    int idx = blockIdx.x * SCHUNK + t;
    int v = (idx < NN) ? g_cursor[idx] : 0;
    sh[t] = v;
    __syncthreads();
    for (int off = 1; off < SCHUNK; off <<= 1) {
        int u = (t >= off) ? sh[t - off] : 0;
        __syncthreads();
        sh[t] += u;
        __syncthreads();
    }
    if (idx < NN) g_rowptr[idx] = sh[t] - v;
    if (t == SCHUNK - 1) g_partials[blockIdx.x] = sh[SCHUNK - 1];
}
__global__ void k_scan2(void) {
    int acc = 0;
    for (int b = 0; b < NCHUNK; b++) { int v = g_partials[b]; g_partials[b] = acc; acc += v; }
}
__global__ void k_scan3(void) {
    int i = blockIdx.x * blockDim.x + threadIdx.x;
    if (i < NN) {
        int r = g_rowptr[i] + g_partials[i >> 9];
        g_rowptr[i] = r; g_cursor[i] = r;
    }
    if (i == 0) g_rowptr[NN] = NE;
}
__global__ void k_fill(const float* __restrict__ w) {
    int e = blockIdx.x * blockDim.x + threadIdx.x;
    if (e >= NE) return;
    int d = g_dst[e], s = g_src[e];
    int pos = atomicAdd(&g_cursor[d], 1);
    g_csrsrc[pos]  = s;
    g_csrcoef[pos] = g_dis[s] * w[e] * g_dis[d];
}
__global__ void k_layer1(const float* __restrict__ x,
                         const float* __restrict__ W1,
                         const float* __restrict__ b1) {
    int gt = blockIdx.x * blockDim.x + threadIdx.x;
    int node = gt >> 5, lane = gt & 31;
    if (node >= NN) return;
    int s0 = g_rowptr[node], s1 = g_rowptr[node + 1];
    float p = 0.f;
    for (int j = s0 + lane; j < s1; j += 32)
        p = fmaf(g_csrcoef[j], x[g_csrsrc[j]], p);
    #pragma unroll
    for (int o = 16; o; o >>= 1) p += __shfl_xor_sync(0xFFFFFFFFu, p, o);
    float dd = g_dis[node];
    float a = p + dd * dd * x[node];
    size_t base = (size_t)node * HID;
    #pragma unroll
    for (int k = 0; k < 4; k++) {
        int f = lane + 32 * k;
        g_h1[base + f] = fmaxf(fmaf(a, W1[f], b1[f]), 0.f);
    }
}
__global__ void k_agg(void) {          // R1 simple version (<<<NN,128>>>)
    int node = blockIdx.x;
    int f = threadIdx.x;
    float dd = g_dis[node];
    float acc = dd * dd * g_h1[(size_t)node * HID + f];
    int s0 = g_rowptr[node], s1 = g_rowptr[node + 1];
    for (int j = s0; j < s1; j++)
        acc = fmaf(g_csrcoef[j], g_h1[(size_t)g_csrsrc[j] * HID + f], acc);
    g_agg[(size_t)node * HID + f] = acc;
}

// ================= weight pre-split (transpose + bf16 hi/lo) ==================
__global__ void k_wconv(const float* __restrict__ W2, const float* __restrict__ Wl1) {
    int i = blockIdx.x * blockDim.x + threadIdx.x;
    if (i < 256 * 128) {
        int n = i >> 7, k = i & 127;
        float v = W2[k * 256 + n];
        __nv_bfloat16 h = __float2bfloat16(v);
        g_W2T_hi[n * 128 + k] = __bfloat16_as_ushort(h);
        g_W2T_lo[n * 128 + k] =
            __bfloat16_as_ushort(__float2bfloat16(v - __bfloat162float(h)));
    } else if (i < 256 * 128 + 128 * 256) {
        int j = i - 256 * 128;
        int n = j >> 8, k = j & 255;
        float v = Wl1[k * 128 + n];
        __nv_bfloat16 h = __float2bfloat16(v);
        g_Wl1T_hi[n * 256 + k] = __bfloat16_as_ushort(h);
        g_Wl1T_lo[n * 256 + k] =
            __bfloat16_as_ushort(__float2bfloat16(v - __bfloat162float(h)));
    }
}

// ================= tensor-core MLP (mma.sync bf16, 3-term hi/lo) ==============
// smem layout (bytes):
//   [0,1024)       b2s (256 f32)
//   [1024,1536)    bl1s (128 f32)
//   [1536,2048)    wl2s (128 f32)
//   [2048, +34816) Bsm_hi  : [128 rows][68 words] (row stride 272B, ≡4 mod 32 words)
//   [36864,+34816) Bsm_lo
//   [71680,+67584) h2_hi   : [128 rows][132 words] (row stride 528B, ≡4 mod 32 words)
//   [139264,+67584) h2_lo
//   h3 (f32 [128][132w]) aliases Bsm region at 2048 (written after last Bsm use)
#define O_BH   2048
#define O_BL   (2048 + 34816)
#define O_H2H  (2048 + 2 * 34816)
#define O_H2L  (O_H2H + 67584)
#define SM_TOT (O_H2L + 67584)
#define O_H3   O_BH
#define MT2    128
#define NTILE2 ((NN + MT2 - 1) / MT2)

__device__ __forceinline__ void mma4(float* c, const uint32_t* a,
                                     uint32_t b0, uint32_t b1) {
    asm volatile(
        "mma.sync.aligned.m16n8k16.row.col.f32.bf16.bf16.f32 "
        "{%0,%1,%2,%3}, {%4,%5,%6,%7}, {%8,%9}, {%0,%1,%2,%3};"
        : "+f"(c[0]), "+f"(c[1]), "+f"(c[2]), "+f"(c[3])
        : "r"(a[0]), "r"(a[1]), "r"(a[2]), "r"(a[3]), "r"(b0), "r"(b1));
}
__device__ __forceinline__ void split2(float x, float y, uint32_t& h, uint32_t& l) {
    __nv_bfloat16 hx = __float2bfloat16(x), hy = __float2bfloat16(y);
    h = (uint32_t)__bfloat16_as_ushort(hx) | ((uint32_t)__bfloat16_as_ushort(hy) << 16);
    __nv_bfloat16 lx = __float2bfloat16(x - __bfloat162float(hx));
    __nv_bfloat16 ly = __float2bfloat16(y - __bfloat162float(hy));
    l = (uint32_t)__bfloat16_as_ushort(lx) | ((uint32_t)__bfloat16_as_ushort(ly) << 16);
}
__device__ __forceinline__ void stageB(char* smem, const unsigned short* srch,
                                       const unsigned short* srcl, int rows,
                                       int sstride, int tid) {
    uint32_t* dh = (uint32_t*)(smem + O_BH);
    uint32_t* dl = (uint32_t*)(smem + O_BL);
    int total = rows * 16;                       // uint4 chunks per buffer
    for (int i = tid; i < total; i += 256) {
        int r = i >> 4, q = i & 15;
        uint4 v = *(const uint4*)(srch + r * sstride + q * 8);
        *(uint4*)(dh + r * 68 + q * 4) = v;
        uint4 w2 = *(const uint4*)(srcl + r * sstride + q * 8);
        *(uint4*)(dl + r * 68 + q * 4) = w2;
    }
}

__global__ __launch_bounds__(256, 1) void k_mlp_tc(
        const float* __restrict__ b2,  const float* __restrict__ bl1,
        const float* __restrict__ Wl2, const float* __restrict__ bl2,
        float* __restrict__ out) {
    extern __shared__ char smem[];
    int tid = threadIdx.x, wid = tid >> 5, lane = tid & 31;
    int g = lane >> 2, tig = lane & 3;
    float* b2s  = (float*)smem;
    float* bl1s = (float*)(smem + 1024);
    float* wl2s = (float*)(smem + 1536);
    b2s[tid] = b2[tid];
    if (tid < 128) { bl1s[tid] = bl1[tid]; wl2s[tid] = Wl2[tid]; }

    int tile0 = blockIdx.x * MT2;
    int m0 = wid * 16;
    int rA = tile0 + m0 + g;
    int rB = rA + 8;
    rA = rA < NN ? rA : NN - 1;                  // clamp; garbage rows never stored
    rB = rB < NN ? rB : NN - 1;
    const float* aggA = g_agg + (size_t)rA * 128;
    const float* aggB = g_agg + (size_t)rB * 128;
    uint32_t* h2h = (uint32_t*)(smem + O_H2H);
    uint32_t* h2l = (uint32_t*)(smem + O_H2L);
    const uint32_t* Bh = (const uint32_t*)(smem + O_BH);
    const uint32_t* Bl = (const uint32_t*)(smem + O_BL);

    // ---------------- GEMM1: h2 = relu(agg @ W2 + b2), 4 n-chunks of 64 -------
    for (int nc = 0; nc < 4; nc++) {
        __syncthreads();                          // Bsm reuse / misc staging
        stageB(smem, g_W2T_hi + nc * 64 * 128, g_W2T_lo + nc * 64 * 128, 64, 128, tid);
        __syncthreads();
        float c1[32];
        #pragma unroll
        for (int i = 0; i < 32; i++) c1[i] = 0.f;
        #pragma unroll
        for (int ks = 0; ks < 8; ks++) {
            int k0 = ks * 16 + tig * 2;
            float2 vA0 = *(const float2*)(aggA + k0);
            float2 vB0 = *(const float2*)(aggB + k0);
            float2 vA1 = *(const float2*)(aggA + k0 + 8);
            float2 vB1 = *(const float2*)(aggB + k0 + 8);
            uint32_t ah[4], al[4];
            split2(vA0.x, vA0.y, ah[0], al[0]);
            split2(vB0.x, vB0.y, ah[1], al[1]);
            split2(vA1.x, vA1.y, ah[2], al[2]);
            split2(vB1.x, vB1.y, ah[3], al[3]);
            #pragma unroll
            for (int nt = 0; nt < 8; nt++) {
                int bw = (nt * 8 + g) * 68 + ks * 8 + tig;
                uint32_t bh0 = Bh[bw], bh1 = Bh[bw + 4];
                uint32_t bl0 = Bl[bw], bl1r = Bl[bw + 4];
                mma4(c1 + nt * 4, ah, bh0, bh1);
                mma4(c1 + nt * 4, al, bh0, bh1);
                mma4(c1 + nt * 4, ah, bl0, bl1r);
            }
        }
        // epilogue: +b2, relu, bf16 hi/lo -> h2 smem
        #pragma unroll
        for (int nt = 0; nt < 8; nt++) {
            int col = nc * 64 + nt * 8 + tig * 2;
            int cw  = nc * 32 + nt * 4 + tig;
            float v0 = fmaxf(c1[nt * 4 + 0] + b2s[col],     0.f);
            float v1 = fmaxf(c1[nt * 4 + 1] + b2s[col + 1], 0.f);
            float v2 = fmaxf(c1[nt * 4 + 2] + b2s[col],     0.f);
            float v3 = fmaxf(c1[nt * 4 + 3] + b2s[col + 1], 0.f);
            uint32_t h, l;
            int w0 = (m0 + g) * 132 + cw;
            int w1 = (m0 + g + 8) * 132 + cw;
            split2(v0, v1, h, l); h2h[w0] = h; h2l[w0] = l;
            split2(v2, v3, h, l); h2h[w1] = h; h2l[w1] = l;
        }
    }

    // ---------------- GEMM2: h3 = relu(h2 @ Wl1 + bl1), 2 k-chunks of 128 -----
    float c2[64];
    #pragma unroll
    for (int i = 0; i < 64; i++) c2[i] = 0.f;
    for (int kc = 0; kc < 2; kc++) {
        __syncthreads();
        stageB(smem, g_Wl1T_hi + kc * 128, g_Wl1T_lo + kc * 128, 128, 256, tid);
        __syncthreads();
        int ra = (m0 + g) * 132, rb = (m0 + g + 8) * 132;
        #pragma unroll
        for (int ks = 0; ks < 8; ks++) {
            int kw = kc * 64 + ks * 8 + tig;
            uint32_t ah[4], al[4];
            ah[0] = h2h[ra + kw];     ah[1] = h2h[rb + kw];
            ah[2] = h2h[ra + kw + 4]; ah[3] = h2h[rb + kw + 4];
            al[0] = h2l[ra + kw];     al[1] = h2l[rb + kw];
            al[2] = h2l[ra + kw + 4]; al[3] = h2l[rb + kw + 4];
            #pragma unroll
            for (int nt = 0; nt < 16; nt++) {
                int bw = (nt * 8 + g) * 68 + ks * 8 + tig;
                uint32_t bh0 = Bh[bw], bh1 = Bh[bw + 4];
                uint32_t bl0 = Bl[bw], bl1r = Bl[bw + 4];
                mma4(c2 + nt * 4, ah, bh0, bh1);
                mma4(c2 + nt * 4, al, bh0, bh1);
                mma4(c2 + nt * 4, ah, bl0, bl1r);
            }
        }
    }
    __syncthreads();                              // Bsm region now free
    // h3 (f32) into aliased region
    float* h3 = (float*)(smem + O_H3);
    {
        int r0 = (m0 + g) * 132, r1 = (m0 + g + 8) * 132;
        #pragma unroll
        for (int nt = 0; nt < 16; nt++) {
            int col = nt * 8 + tig * 2;
            h3[r0 + col]     = fmaxf(c2[nt * 4 + 0] + bl1s[col],     0.f);
            h3[r0 + col + 1] = fmaxf(c2[nt * 4 + 1] + bl1s[col + 1], 0.f);
            h3[r1 + col]     = fmaxf(c2[nt * 4 + 2] + bl1s[col],     0.f);
            h3[r1 + col + 1] = fmaxf(c2[nt * 4 + 3] + bl1s[col + 1], 0.f);
        }
    }
    __syncthreads();
    // ---------------- GEMM3: out = h3 . Wl2 + bl2 -----------------------------
    float bl2v = bl2[0];
    for (int r = 0; r < 16; r++) {
        int row = m0 + r;
        int node = tile0 + row;
        float s = 0.f;
        #pragma unroll
        for (int q = 0; q < 4; q++)
            s = fmaf(h3[row * 132 + lane + 32 * q], wl2s[lane + 32 * q], s);
        #pragma unroll
        for (int o = 16; o; o >>= 1) s += __shfl_xor_sync(0xFFFFFFFFu, s, o);
        if (lane == 0 && node < NN) out[node] = s + bl2v;
    }
}

// ---------------- launch ------------------------------------------------------
extern "C" void kernel_launch(void* const* d_in, const int* in_sizes, int n_in,
                              void* d_out, int out_size) {
    const float* x   = (const float*)d_in[0];
    const void*  ei  = d_in[1];
    const float* w   = (const float*)d_in[2];
    const float* W1  = (const float*)d_in[3];
    const float* b1  = (const float*)d_in[4];
    const float* W2  = (const float*)d_in[5];
    const float* b2  = (const float*)d_in[6];
    const float* Wl1 = (const float*)d_in[7];
    const float* bl1 = (const float*)d_in[8];
    const float* Wl2 = (const float*)d_in[9];
    const float* bl2 = (const float*)d_in[10];
    float* out = (float*)d_out;

    const int TB = 256;
    const int EB = (NE + TB - 1) / TB;
    const int VB = (NN + TB - 1) / TB;

    static int smem_set = 0;
    if (!smem_set) {
        cudaFuncSetAttribute(k_mlp_tc, cudaFuncAttributeMaxDynamicSharedMemorySize, SM_TOT);
        smem_set = 1;
    }

    k_detect <<<1, 32>>>(ei);
    k_convert<<<EB, TB>>>(ei);
    k_init   <<<VB, TB>>>();
    k_wconv  <<<256, TB>>>(W2, Wl1);
    k_deg    <<<EB, TB>>>(w);
    k_rsqrt  <<<VB, TB>>>();
    k_scan1  <<<NCHUNK, SCHUNK>>>();
    k_scan2  <<<1, 1>>>();
    k_scan3  <<<VB, TB>>>();
    k_fill   <<<EB, TB>>>(w);
    k_layer1 <<<(NN * 32 + TB - 1) / TB, TB>>>(x, W1, b1);
    k_agg    <<<NN, HID>>>();
    k_mlp_tc <<<NTILE2, TB, SM_TOT>>>(b2, bl1, Wl2, bl2, out);
}

// round 16
// speedup vs baseline: 2.3553x; 1.0028x over previous
#include <cuda_runtime.h>
#include <cuda_bf16.h>
#include <stdint.h>

#define NN 100000
#define NE 1600000
#define HID 128

// ---------------- device scratch ----------------
__device__ int   g_src[NE];
__device__ int   g_dst[NE];
__device__ float g_dis[NN];
__device__ int   g_cursor[NN];
__device__ int   g_rowptr[NN + 1];
__device__ int   g_partials[256];
__device__ __align__(16) int2 g_edge[NE];        // packed (src, coef-bits)
__device__ float g_a1[NN];
__device__ __align__(16) float g_h1[(size_t)NN * HID];
__device__ __align__(16) float g_agg[(size_t)NN * HID];
// pre-split transposed weights (bf16 hi/lo)
__device__ __align__(16) unsigned short g_W2T_hi[256 * 128];
__device__ __align__(16) unsigned short g_W2T_lo[256 * 128];
__device__ __align__(16) unsigned short g_Wl1T_hi[128 * 256];
__device__ __align__(16) unsigned short g_Wl1T_lo[128 * 256];

// ================= front-end ==================================================
__global__ void k_init(void) {
    int i = blockIdx.x * blockDim.x + threadIdx.x;
    if (i < NN) { g_dis[i] = 1.0f; g_cursor[i] = 0; g_a1[i] = 0.f; }
}

// convert (inline dtype detect) + degree accumulation
__global__ void k_conv_deg(const void* ei, const float* __restrict__ w) {
    __shared__ int sflag;
    int t = threadIdx.x;
    if (t < 32) {
        const long long* p = (const long long*)ei;
        long long v = p[(long long)t * (NE / 32)];
        bool ok = (v >= 0 && v < NN);
        unsigned m = __ballot_sync(0xFFFFFFFFu, ok);
        if (t == 0) sflag = (m == 0xFFFFFFFFu) ? 1 : 0;
    }
    __syncthreads();
    int e = blockIdx.x * blockDim.x + t;
    if (e >= NE) return;
    int s, d;
    if (sflag) {
        const long long* p = (const long long*)ei;
        s = (int)p[e]; d = (int)p[e + NE];
    } else {
        const int* p = (const int*)ei;
        s = p[e]; d = p[e + NE];
    }
    g_src[e] = s; g_dst[e] = d;
    atomicAdd(&g_dis[d], w[e]);
    atomicAdd(&g_cursor[d], 1);
}

#define SCHUNK 512
#define NCHUNK ((NN + SCHUNK - 1) / SCHUNK)
__global__ void k_scan1(void) {
    __shared__ int sh[SCHUNK];
    int t = threadIdx.x;
    int idx = blockIdx.x * SCHUNK + t;
    int v = (idx < NN) ? g_cursor[idx] : 0;
    sh[t] = v;
    __syncthreads();
    for (int off = 1; off < SCHUNK; off <<= 1) {
        int u = (t >= off) ? sh[t - off] : 0;
        __syncthreads();
        sh[t] += u;
        __syncthreads();
    }
    if (idx < NN) g_rowptr[idx] = sh[t] - v;
    if (t == SCHUNK - 1) g_partials[blockIdx.x] = sh[SCHUNK - 1];
}
__global__ void k_scan2(void) {
    int acc = 0;
    for (int b = 0; b < NCHUNK; b++) { int v = g_partials[b]; g_partials[b] = acc; acc += v; }
}
__global__ void k_scan3(void) {       // + rsqrt fold
    int i = blockIdx.x * blockDim.x + threadIdx.x;
    if (i < NN) {
        int r = g_rowptr[i] + g_partials[i >> 9];
        g_rowptr[i] = r; g_cursor[i] = r;
        g_dis[i] = rsqrtf(g_dis[i]);
    }
    if (i == 0) g_rowptr[NN] = NE;
}

// CSR fill (packed int2) + layer-1 scalar aggregation
__global__ void k_fill(const float* __restrict__ w, const float* __restrict__ x) {
    int e = blockIdx.x * blockDim.x + threadIdx.x;
    if (e >= NE) return;
    int d = g_dst[e], s = g_src[e];
    float c = g_dis[s] * w[e] * g_dis[d];
    int pos = atomicAdd(&g_cursor[d], 1);
    g_edge[pos] = make_int2(s, __float_as_int(c));
    atomicAdd(&g_a1[d], c * __ldg(&x[s]));
}

// expand scalar a1 -> h1 (warp per node, float4 stores)
__global__ void k_expand(const float* __restrict__ x,
                         const float* __restrict__ W1,
                         const float* __restrict__ b1) {
    int gt = blockIdx.x * blockDim.x + threadIdx.x;
    int node = gt >> 5, lane = gt & 31;
    if (node >= NN) return;
    float dd = g_dis[node];
    float a  = g_a1[node] + dd * dd * x[node];
    float4* dst = (float4*)(g_h1 + (size_t)node * HID);
    const float4* W4 = (const float4*)W1;
    const float4* b4 = (const float4*)b1;
    // lane covers 32 float4 slots (128 floats)
    float4 wv = W4[lane], bv = b4[lane];
    float4 o;
    o.x = fmaxf(fmaf(a, wv.x, bv.x), 0.f);
    o.y = fmaxf(fmaf(a, wv.y, bv.y), 0.f);
    o.z = fmaxf(fmaf(a, wv.z, bv.z), 0.f);
    o.w = fmaxf(fmaf(a, wv.w, bv.w), 0.f);
    dst[lane] = o;
}

// layer-2 SpMM: block per node, prefetch-4 packed edges
__global__ __launch_bounds__(HID) void k_agg(void) {   // <<<NN, 128>>>
    int node = blockIdx.x;
    int f = threadIdx.x;
    float dd = g_dis[node];
    float acc = dd * dd * g_h1[(size_t)node * HID + f];
    int j = g_rowptr[node], e = g_rowptr[node + 1];
    for (; j + 4 <= e; j += 4) {
        int2 e0 = g_edge[j],     e1 = g_edge[j + 1];
        int2 e2 = g_edge[j + 2], e3 = g_edge[j + 3];
        float h0 = g_h1[(size_t)e0.x * HID + f];
        float h1 = g_h1[(size_t)e1.x * HID + f];
        float h2 = g_h1[(size_t)e2.x * HID + f];
        float h3 = g_h1[(size_t)e3.x * HID + f];
        acc = fmaf(__int_as_float(e0.y), h0, acc);
        acc = fmaf(__int_as_float(e1.y), h1, acc);
        acc = fmaf(__int_as_float(e2.y), h2, acc);
        acc = fmaf(__int_as_float(e3.y), h3, acc);
    }
    for (; j < e; j++) {
        int2 ee = g_edge[j];
        acc = fmaf(__int_as_float(ee.y), g_h1[(size_t)ee.x * HID + f], acc);
    }
    g_agg[(size_t)node * HID + f] = acc;
}

// ================= weight pre-split (transpose + bf16 hi/lo) ==================
__global__ void k_wconv(const float* __restrict__ W2, const float* __restrict__ Wl1) {
    int i = blockIdx.x * blockDim.x + threadIdx.x;
    if (i < 256 * 128) {
        int n = i >> 7, k = i & 127;
        float v = W2[k * 256 + n];
        __nv_bfloat16 h = __float2bfloat16(v);
        g_W2T_hi[n * 128 + k] = __bfloat16_as_ushort(h);
        g_W2T_lo[n * 128 + k] =
            __bfloat16_as_ushort(__float2bfloat16(v - __bfloat162float(h)));
    } else if (i < 256 * 128 + 128 * 256) {
        int j = i - 256 * 128;
        int n = j >> 8, k = j & 255;
        float v = Wl1[k * 128 + n];
        __nv_bfloat16 h = __float2bfloat16(v);
        g_Wl1T_hi[n * 256 + k] = __bfloat16_as_ushort(h);
        g_Wl1T_lo[n * 256 + k] =
            __bfloat16_as_ushort(__float2bfloat16(v - __bfloat162float(h)));
    }
}

// ================= tensor-core MLP (mma.sync bf16, 3-term hi/lo) ==============
// smem layout (bytes):
//   [0,1024)       b2s (256 f32)
//   [1024,1536)    bl1s (128 f32)
//   [1536,2048)    wl2s (128 f32)
//   [2048, +34816) Bsm_hi  : [128 rows][68 words]
//   [36864,+34816) Bsm_lo
//   [71680,+67584) h2_hi   : [128 rows][132 words]
//   [139264,+67584) h2_lo
//   h3 (f32 [128][132w]) aliases Bsm region at 2048
#define O_BH   2048
#define O_BL   (2048 + 34816)
#define O_H2H  (2048 + 2 * 34816)
#define O_H2L  (O_H2H + 67584)
#define SM_TOT (O_H2L + 67584)
#define O_H3   O_BH
#define MT2    128
#define NTILE2 ((NN + MT2 - 1) / MT2)

__device__ __forceinline__ void mma4(float* c, const uint32_t* a,
                                     uint32_t b0, uint32_t b1) {
    asm volatile(
        "mma.sync.aligned.m16n8k16.row.col.f32.bf16.bf16.f32 "
        "{%0,%1,%2,%3}, {%4,%5,%6,%7}, {%8,%9}, {%0,%1,%2,%3};"
        : "+f"(c[0]), "+f"(c[1]), "+f"(c[2]), "+f"(c[3])
        : "r"(a[0]), "r"(a[1]), "r"(a[2]), "r"(a[3]), "r"(b0), "r"(b1));
}
__device__ __forceinline__ void split2(float x, float y, uint32_t& h, uint32_t& l) {
    __nv_bfloat16 hx = __float2bfloat16(x), hy = __float2bfloat16(y);
    h = (uint32_t)__bfloat16_as_ushort(hx) | ((uint32_t)__bfloat16_as_ushort(hy) << 16);
    __nv_bfloat16 lx = __float2bfloat16(x - __bfloat162float(hx));
    __nv_bfloat16 ly = __float2bfloat16(y - __bfloat162float(hy));
    l = (uint32_t)__bfloat16_as_ushort(lx) | ((uint32_t)__bfloat16_as_ushort(ly) << 16);
}
__device__ __forceinline__ void stageB(char* smem, const unsigned short* srch,
                                       const unsigned short* srcl, int rows,
                                       int sstride, int tid) {
    uint32_t* dh = (uint32_t*)(smem + O_BH);
    uint32_t* dl = (uint32_t*)(smem + O_BL);
    int total = rows * 16;
    for (int i = tid; i < total; i += 256) {
        int r = i >> 4, q = i & 15;
        uint4 v = *(const uint4*)(srch + r * sstride + q * 8);
        *(uint4*)(dh + r * 68 + q * 4) = v;
        uint4 w2 = *(const uint4*)(srcl + r * sstride + q * 8);
        *(uint4*)(dl + r * 68 + q * 4) = w2;
    }
}

__global__ __launch_bounds__(256, 1) void k_mlp_tc(
        const float* __restrict__ b2,  const float* __restrict__ bl1,
        const float* __restrict__ Wl2, const float* __restrict__ bl2,
        float* __restrict__ out) {
    extern __shared__ char smem[];
    int tid = threadIdx.x, wid = tid >> 5, lane = tid & 31;
    int g = lane >> 2, tig = lane & 3;
    float* b2s  = (float*)smem;
    float* bl1s = (float*)(smem + 1024);
    float* wl2s = (float*)(smem + 1536);
    b2s[tid] = b2[tid];
    if (tid < 128) { bl1s[tid] = bl1[tid]; wl2s[tid] = Wl2[tid]; }

    int tile0 = blockIdx.x * MT2;
    int m0 = wid * 16;
    int rA = tile0 + m0 + g;
    int rB = rA + 8;
    rA = rA < NN ? rA : NN - 1;
    rB = rB < NN ? rB : NN - 1;
    const float* aggA = g_agg + (size_t)rA * 128;
    const float* aggB = g_agg + (size_t)rB * 128;
    uint32_t* h2h = (uint32_t*)(smem + O_H2H);
    uint32_t* h2l = (uint32_t*)(smem + O_H2L);
    const uint32_t* Bh = (const uint32_t*)(smem + O_BH);
    const uint32_t* Bl = (const uint32_t*)(smem + O_BL);

    // ---------------- GEMM1: h2 = relu(agg @ W2 + b2), 4 n-chunks of 64 -------
    for (int nc = 0; nc < 4; nc++) {
        __syncthreads();
        stageB(smem, g_W2T_hi + nc * 64 * 128, g_W2T_lo + nc * 64 * 128, 64, 128, tid);
        __syncthreads();
        float c1[32];
        #pragma unroll
        for (int i = 0; i < 32; i++) c1[i] = 0.f;
        #pragma unroll
        for (int ks = 0; ks < 8; ks++) {
            int k0 = ks * 16 + tig * 2;
            float2 vA0 = *(const float2*)(aggA + k0);
            float2 vB0 = *(const float2*)(aggB + k0);
            float2 vA1 = *(const float2*)(aggA + k0 + 8);
            float2 vB1 = *(const float2*)(aggB + k0 + 8);
            uint32_t ah[4], al[4];
            split2(vA0.x, vA0.y, ah[0], al[0]);
            split2(vB0.x, vB0.y, ah[1], al[1]);
            split2(vA1.x, vA1.y, ah[2], al[2]);
            split2(vB1.x, vB1.y, ah[3], al[3]);
            #pragma unroll
            for (int nt = 0; nt < 8; nt++) {
                int bw = (nt * 8 + g) * 68 + ks * 8 + tig;
                uint32_t bh0 = Bh[bw], bh1 = Bh[bw + 4];
                uint32_t bl0 = Bl[bw], bl1r = Bl[bw + 4];
                mma4(c1 + nt * 4, ah, bh0, bh1);
                mma4(c1 + nt * 4, al, bh0, bh1);
                mma4(c1 + nt * 4, ah, bl0, bl1r);
            }
        }
        #pragma unroll
        for (int nt = 0; nt < 8; nt++) {
            int col = nc * 64 + nt * 8 + tig * 2;
            int cw  = nc * 32 + nt * 4 + tig;
            float v0 = fmaxf(c1[nt * 4 + 0] + b2s[col],     0.f);
            float v1 = fmaxf(c1[nt * 4 + 1] + b2s[col + 1], 0.f);
            float v2 = fmaxf(c1[nt * 4 + 2] + b2s[col],     0.f);
            float v3 = fmaxf(c1[nt * 4 + 3] + b2s[col + 1], 0.f);
            uint32_t h, l;
            int w0 = (m0 + g) * 132 + cw;
            int w1 = (m0 + g + 8) * 132 + cw;
            split2(v0, v1, h, l); h2h[w0] = h; h2l[w0] = l;
            split2(v2, v3, h, l); h2h[w1] = h; h2l[w1] = l;
        }
    }

    // ---------------- GEMM2: h3 = relu(h2 @ Wl1 + bl1), 2 k-chunks of 128 -----
    float c2[64];
    #pragma unroll
    for (int i = 0; i < 64; i++) c2[i] = 0.f;
    for (int kc = 0; kc < 2; kc++) {
        __syncthreads();
        stageB(smem, g_Wl1T_hi + kc * 128, g_Wl1T_lo + kc * 128, 128, 256, tid);
        __syncthreads();
        int ra = (m0 + g) * 132, rb = (m0 + g + 8) * 132;
        #pragma unroll
        for (int ks = 0; ks < 8; ks++) {
            int kw = kc * 64 + ks * 8 + tig;
            uint32_t ah[4], al[4];
            ah[0] = h2h[ra + kw];     ah[1] = h2h[rb + kw];
            ah[2] = h2h[ra + kw + 4]; ah[3] = h2h[rb + kw + 4];
            al[0] = h2l[ra + kw];     al[1] = h2l[rb + kw];
            al[2] = h2l[ra + kw + 4]; al[3] = h2l[rb + kw + 4];
            #pragma unroll
            for (int nt = 0; nt < 16; nt++) {
                int bw = (nt * 8 + g) * 68 + ks * 8 + tig;
                uint32_t bh0 = Bh[bw], bh1 = Bh[bw + 4];
                uint32_t bl0 = Bl[bw], bl1r = Bl[bw + 4];
                mma4(c2 + nt * 4, ah, bh0, bh1);
                mma4(c2 + nt * 4, al, bh0, bh1);
                mma4(c2 + nt * 4, ah, bl0, bl1r);
            }
        }
    }
    __syncthreads();
    float* h3 = (float*)(smem + O_H3);
    {
        int r0 = (m0 + g) * 132, r1 = (m0 + g + 8) * 132;
        #pragma unroll
        for (int nt = 0; nt < 16; nt++) {
            int col = nt * 8 + tig * 2;
            h3[r0 + col]     = fmaxf(c2[nt * 4 + 0] + bl1s[col],     0.f);
            h3[r0 + col + 1] = fmaxf(c2[nt * 4 + 1] + bl1s[col + 1], 0.f);
            h3[r1 + col]     = fmaxf(c2[nt * 4 + 2] + bl1s[col],     0.f);
            h3[r1 + col + 1] = fmaxf(c2[nt * 4 + 3] + bl1s[col + 1], 0.f);
        }
    }
    __syncthreads();
    float bl2v = bl2[0];
    for (int r = 0; r < 16; r++) {
        int row = m0 + r;
        int node = tile0 + row;
        float s = 0.f;
        #pragma unroll
        for (int q = 0; q < 4; q++)
            s = fmaf(h3[row * 132 + lane + 32 * q], wl2s[lane + 32 * q], s);
        #pragma unroll
        for (int o = 16; o; o >>= 1) s += __shfl_xor_sync(0xFFFFFFFFu, s, o);
        if (lane == 0 && node < NN) out[node] = s + bl2v;
    }
}

// ---------------- launch ------------------------------------------------------
extern "C" void kernel_launch(void* const* d_in, const int* in_sizes, int n_in,
                              void* d_out, int out_size) {
    const float* x   = (const float*)d_in[0];
    const void*  ei  = d_in[1];
    const float* w   = (const float*)d_in[2];
    const float* W1  = (const float*)d_in[3];
    const float* b1  = (const float*)d_in[4];
    const float* W2  = (const float*)d_in[5];
    const float* b2  = (const float*)d_in[6];
    const float* Wl1 = (const float*)d_in[7];
    const float* bl1 = (const float*)d_in[8];
    const float* Wl2 = (const float*)d_in[9];
    const float* bl2 = (const float*)d_in[10];
    float* out = (float*)d_out;

    const int TB = 256;
    const int EB = (NE + TB - 1) / TB;
    const int VB = (NN + TB - 1) / TB;

    static int smem_set = 0;
    if (!smem_set) {
        cudaFuncSetAttribute(k_mlp_tc, cudaFuncAttributeMaxDynamicSharedMemorySize, SM_TOT);
        smem_set = 1;
    }

    k_init    <<<VB, TB>>>();
    k_wconv   <<<256, TB>>>(W2, Wl1);
    k_conv_deg<<<EB, TB>>>(ei, w);
    k_scan1   <<<NCHUNK, SCHUNK>>>();
    k_scan2   <<<1, 1>>>();
    k_scan3   <<<VB, TB>>>();
    k_fill    <<<EB, TB>>>(w, x);
    k_expand  <<<(NN * 32 + TB - 1) / TB, TB>>>(x, W1, b1);
    k_agg     <<<NN, HID>>>();
    k_mlp_tc  <<<NTILE2, TB, SM_TOT>>>(b2, bl1, Wl2, bl2, out);
}